// round 2
// baseline (speedup 1.0000x reference)
#include <cuda_runtime.h>

#define Nn 2048
#define Ee 65536

// ---------------- scratch (device globals; no allocations) ----------------
__device__ __align__(16) float g_x[Nn*64];
__device__ __align__(16) float g_xW[Nn*128];
__device__ __align__(16) float g_xr[Nn];
__device__ __align__(16) float g_ealpha[Ee];
__device__ __align__(16) float g_S[Nn*128];
__device__ __align__(16) float g_h1[Nn*128];
__device__ __align__(16) float g_h2[Nn*128];
__device__ __align__(16) float g_feat[Nn*320];
__device__ __align__(16) float g_a20[Nn*20];
__device__ __align__(16) float g_b20[Nn*20];
__device__ __align__(16) float g_W1p[40*320];
__device__ __align__(16) float g_w1e[256];      // [0:128) layer0 last-col, [128:256) layer1
__device__ int g_deg[Nn];
__device__ int g_off[Nn+1];
__device__ int g_cur[Nn];
__device__ int g_perm[Ee];

__device__ __forceinline__ float lrelu(float x) { return x > 0.f ? x : 0.01f*x; }

__device__ __forceinline__ float* sel_ptr(int s) {
  switch (s) {
    case 0: return g_x;
    case 1: return g_S;
    case 2: return g_h1;
    case 3: return g_feat;
    case 4: return g_xW;
    case 5: return g_a20;
    case 6: return g_b20;
    case 7: return g_W1p;
    case 8: return g_h2;
    default: return nullptr;
  }
}

// ---------------- misc small kernels ----------------
__global__ void k_zero() {
  int i = blockIdx.x*256 + threadIdx.x;
  if (i < Nn) g_deg[i] = 0;
}

__global__ void k_embed(const int* __restrict__ ids, const float* __restrict__ emb) {
  g_x[blockIdx.x*64 + threadIdx.x] = emb[ids[blockIdx.x]*64 + threadIdx.x];
}

__global__ void k_hist(const int* __restrict__ edst) {
  int e = blockIdx.x*256 + threadIdx.x;
  atomicAdd(&g_deg[edst[e]], 1);
}

__global__ void k_scan() {  // Blelloch exclusive scan over 2048 counts
  __shared__ int s[2048];
  int t = threadIdx.x;
  s[2*t]   = g_deg[2*t];
  s[2*t+1] = g_deg[2*t+1];
  int offset = 1;
  for (int d = 1024; d > 0; d >>= 1) {
    __syncthreads();
    if (t < d) {
      int ai = offset*(2*t+1) - 1;
      int bi = offset*(2*t+2) - 1;
      s[bi] += s[ai];
    }
    offset <<= 1;
  }
  __syncthreads();
  if (t == 0) s[2047] = 0;
  for (int d = 1; d < 2048; d <<= 1) {
    offset >>= 1;
    __syncthreads();
    if (t < d) {
      int ai = offset*(2*t+1) - 1;
      int bi = offset*(2*t+2) - 1;
      int tmp = s[ai]; s[ai] = s[bi]; s[bi] += tmp;
    }
  }
  __syncthreads();
  g_off[2*t]   = s[2*t];   g_cur[2*t]   = s[2*t];
  g_off[2*t+1] = s[2*t+1]; g_cur[2*t+1] = s[2*t+1];
  if (t == 0) g_off[2048] = Ee;
}

__global__ void k_scatter(const int* __restrict__ edst) {
  int e = blockIdx.x*256 + threadIdx.x;
  int p = atomicAdd(&g_cur[edst[e]], 1);
  g_perm[p] = e;
}

__global__ void k_packw(const float* __restrict__ l0, const float* __restrict__ l1) {
  int k = threadIdx.x;                  // 128 threads
  g_w1e[k]       = l0[k*65  + 64];
  g_w1e[128 + k] = l1[k*129 + 128];
}

__global__ void k_packW1(const float* __restrict__ W1) {
  int i = blockIdx.x*256 + threadIdx.x;
  if (i >= 40*320) return;
  int r = i / 320, c = i - r*320;
  g_W1p[i] = (r < 20) ? W1[r*640 + c] : W1[(r-20)*640 + 320 + c];
}

__global__ void k_feat() {
  int i = blockIdx.x*256 + threadIdx.x;
  if (i >= Nn*320) return;
  int n = i / 320, c = i - n*320;
  float v;
  if (c < 64)       v = g_x[n*64 + c];
  else if (c < 192) v = g_h1[n*128 + (c-64)];
  else              v = g_h2[n*128 + (c-192)];
  g_feat[i] = v;
}

// xr[n] = x[n,:] . att_r
__global__ void k_xr(int xsel, int D, const float* __restrict__ attr) {
  const float* x = sel_ptr(xsel);
  int n = blockIdx.x*8 + (threadIdx.x >> 5);
  int lane = threadIdx.x & 31;
  float p = 0.f;
  for (int d = lane; d < D; d += 32) p += x[n*D + d]*attr[d];
  #pragma unroll
  for (int s = 16; s > 0; s >>= 1) p += __shfl_xor_sync(0xffffffffu, p, s);
  if (lane == 0) g_xr[n] = p;
}

// ---------------- generic GEMM: C[M,Nc] = act(A[M,K] @ B[Nc,K]^T + bias) ----------------
template<int ACT>
__global__ void gemm_tn(int Asel, int lda,
                        const float* __restrict__ Bext, int Bsel, int boff, int ldb,
                        const float* __restrict__ bias,
                        int Csel, int ldc, int M, int Ncols, int K) {
  const float* A = sel_ptr(Asel);
  const float* B = Bext ? Bext : (sel_ptr(Bsel) + boff);
  float* C = sel_ptr(Csel);
  __shared__ float As[32][65];
  __shared__ float Bs[32][65];
  int tid = threadIdx.x;
  int m0 = blockIdx.y*64, n0 = blockIdx.x*64;
  int tx = tid & 15, ty = tid >> 4;
  float acc[4][4] = {};
  for (int k0 = 0; k0 < K; k0 += 32) {
    #pragma unroll
    for (int i = 0; i < 8; i++) {
      int l = tid + i*256;
      int r = l >> 5, c = l & 31;
      As[c][r] = A[(m0+r)*lda + (k0+c)];
      int rn = n0 + r;
      Bs[c][r] = (rn < Ncols) ? B[rn*ldb + (k0+c)] : 0.f;
    }
    __syncthreads();
    #pragma unroll
    for (int k = 0; k < 32; k++) {
      float av[4], bv[4];
      #pragma unroll
      for (int i = 0; i < 4; i++) av[i] = As[k][ty*4+i];
      #pragma unroll
      for (int j = 0; j < 4; j++) bv[j] = Bs[k][tx*4+j];
      #pragma unroll
      for (int i = 0; i < 4; i++)
        #pragma unroll
        for (int j = 0; j < 4; j++)
          acc[i][j] += av[i]*bv[j];
    }
    __syncthreads();
  }
  #pragma unroll
  for (int i = 0; i < 4; i++) {
    int mm = m0 + ty*4 + i;
    #pragma unroll
    for (int j = 0; j < 4; j++) {
      int nn = n0 + tx*4 + j;
      if (nn < Ncols) {
        float v = acc[i][j];
        if (bias) v += bias[nn];
        if (ACT) v = fmaxf(v, 0.f);
        C[mm*ldc + nn] = v;
      }
    }
  }
}

// ---------------- edge kernels ----------------
// per-edge attention numerator: ealpha[e] = exp(leaky(h_e . att_l + xr[dst]))
__global__ void k_alpha(const int* __restrict__ esrc, const int* __restrict__ edst,
                        const float* __restrict__ eattr,
                        int w1off, const float* __restrict__ attl) {
  int e = blockIdx.x*8 + (threadIdx.x >> 5);
  int lane = threadIdx.x & 31;
  int src = esrc[e];
  float ea = eattr[e];
  const float4* xw4 = (const float4*)g_xW;
  const float4* we4 = (const float4*)(g_w1e + w1off);
  const float4* al4 = (const float4*)attl;
  float4 xv = xw4[src*32 + lane];
  float4 wv = we4[lane];
  float4 av = al4[lane];
  float p = lrelu(xv.x + ea*wv.x)*av.x + lrelu(xv.y + ea*wv.y)*av.y
          + lrelu(xv.z + ea*wv.z)*av.z + lrelu(xv.w + ea*wv.w)*av.w;
  #pragma unroll
  for (int s = 16; s > 0; s >>= 1) p += __shfl_xor_sync(0xffffffffu, p, s);
  if (lane == 0) g_ealpha[e] = __expf(lrelu(p + g_xr[edst[e]]));
}

// per-dst weighted aggregation: S[n,:] = sum_e softmax_weight(e) * h_e  (h recomputed)
__global__ void k_aggr(const int* __restrict__ esrc, const float* __restrict__ eattr,
                       int w1off) {
  int n = blockIdx.x, tid = threadIdx.x;  // 128 threads
  int begin = g_off[n], cnt = g_off[n+1] - begin;
  __shared__ float rbuf[128];
  __shared__ float s_inv;
  float p = 0.f;
  for (int i = tid; i < cnt; i += 128) p += g_ealpha[g_perm[begin+i]];
  rbuf[tid] = p; __syncthreads();
  for (int s = 64; s > 0; s >>= 1) { if (tid < s) rbuf[tid] += rbuf[tid+s]; __syncthreads(); }
  if (tid == 0) s_inv = 1.f/(rbuf[0] + 1e-16f);
  __syncthreads();
  float inv = s_inv;
  int w = tid >> 5, g = tid & 31;     // warp = edge slot, lane = 4-col group
  const float4* xw4 = (const float4*)g_xW;
  const float4* we4 = (const float4*)(g_w1e + w1off);
  float4 wv = we4[g];
  float ax=0.f, ay=0.f, az=0.f, aw=0.f;
  for (int j0 = 0; j0 < cnt; j0 += 4) {
    int j = j0 + w;
    if (j < cnt) {
      int e = g_perm[begin+j];
      float wt = g_ealpha[e]*inv;
      float ea = eattr[e];
      float4 xv = xw4[esrc[e]*32 + g];
      ax += wt*lrelu(xv.x + ea*wv.x);
      ay += wt*lrelu(xv.y + ea*wv.y);
      az += wt*lrelu(xv.z + ea*wv.z);
      aw += wt*lrelu(xv.w + ea*wv.w);
    }
  }
  __shared__ float4 red4[128];
  red4[tid] = make_float4(ax, ay, az, aw);
  __syncthreads();
  if (w == 0) {
    float4 r = red4[g];
    #pragma unroll
    for (int s = 1; s < 4; s++) {
      float4 o = red4[s*32 + g];
      r.x += o.x; r.y += o.y; r.z += o.z; r.w += o.w;
    }
    ((float4*)g_S)[n*32 + g] = r;
  }
}

// ---------------- fused pairwise MLP + masked row softmax ----------------
__global__ void k_final(const float* __restrict__ b1, const float* __restrict__ W2,
                        const float* __restrict__ b2, const float* __restrict__ m,
                        float* __restrict__ out) {
  const int TI = 8;
  __shared__ float ash[TI][20];
  __shared__ float btile[256][21];
  __shared__ float w2s[20];
  __shared__ float2 red[256];
  __shared__ float rowM[TI], rowInv[TI];
  int tid = threadIdx.x;
  int i0 = blockIdx.x * TI;
  if (tid < TI*20) {
    int r = tid / 20, c = tid - r*20;
    ash[r][c] = g_a20[(i0+r)*20 + c] + b1[c];
  }
  if (tid < 20) w2s[tid] = W2[tid];
  float b2v = b2[0];
  float omax[TI], osum[TI];
  #pragma unroll
  for (int r = 0; r < TI; r++) { omax[r] = -1e30f; osum[r] = 0.f; }

  for (int jt = 0; jt < Nn; jt += 256) {
    __syncthreads();
    #pragma unroll
    for (int u = 0; u < 20; u++) {
      int l = u*256 + tid;
      int t = l / 20, c = l - t*20;
      btile[t][c] = g_b20[jt*20 + l];
    }
    __syncthreads();
    int j = jt + tid;
    float bl[20];
    #pragma unroll
    for (int c = 0; c < 20; c++) bl[c] = btile[tid][c];
    #pragma unroll
    for (int r = 0; r < TI; r++) {
      float acc = 0.f;
      #pragma unroll
      for (int c = 0; c < 20; c++) acc += fmaxf(ash[r][c] + bl[c], 0.f) * w2s[c];
      size_t idx = (size_t)(i0+r)*Nn + j;
      float lv = (acc + b2v) * m[idx];
      out[idx] = lv;                       // park raw logit
      float nm = fmaxf(omax[r], lv);       // online softmax
      osum[r] = osum[r]*__expf(omax[r]-nm) + __expf(lv-nm);
      omax[r] = nm;
    }
  }
  // block-level (max,sum) merge per row
  for (int r = 0; r < TI; r++) {
    __syncthreads();
    red[tid] = make_float2(omax[r], osum[r]);
    __syncthreads();
    for (int s = 128; s > 0; s >>= 1) {
      if (tid < s) {
        float2 A = red[tid], B = red[tid+s];
        float M = fmaxf(A.x, B.x);
        red[tid] = make_float2(M, A.y*__expf(A.x-M) + B.y*__expf(B.x-M));
      }
      __syncthreads();
    }
    if (tid == 0) { rowM[r] = red[0].x; rowInv[r] = 1.f/red[0].y; }
  }
  __syncthreads();
  for (int jt = 0; jt < Nn; jt += 256) {
    int j = jt + tid;
    #pragma unroll
    for (int r = 0; r < TI; r++) {
      size_t idx = (size_t)(i0+r)*Nn + j;
      out[idx] = __expf(out[idx] - rowM[r]) * rowInv[r];
    }
  }
}

// ---------------- driver ----------------
extern "C" void kernel_launch(void* const* d_in, const int* in_sizes, int n_in,
                              void* d_out, int out_size) {
  const int*   node_ids = (const int*)  d_in[0];
  const int*   eidx     = (const int*)  d_in[1];
  const float* eattr    = (const float*)d_in[2];
  const float* m        = (const float*)d_in[3];
  const float* emb      = (const float*)d_in[4];
  const float* l0_lin1  = (const float*)d_in[5];
  const float* l0_lin2  = (const float*)d_in[6];
  const float* l0_attl  = (const float*)d_in[7];
  const float* l0_attr  = (const float*)d_in[8];
  const float* l0_bias  = (const float*)d_in[9];
  const float* l1_lin1  = (const float*)d_in[10];
  const float* l1_lin2  = (const float*)d_in[11];
  const float* l1_attl  = (const float*)d_in[12];
  const float* l1_attr  = (const float*)d_in[13];
  const float* l1_bias  = (const float*)d_in[14];
  const float* W1       = (const float*)d_in[15];
  const float* b1       = (const float*)d_in[16];
  const float* W2       = (const float*)d_in[17];
  const float* b2       = (const float*)d_in[18];
  float* out = (float*)d_out;
  const int* esrc = eidx;
  const int* edst = eidx + Ee;

  // CSR build + embedding + weight packing
  k_zero   <<<8, 256>>>();
  k_embed  <<<Nn, 64>>>(node_ids, emb);
  k_hist   <<<Ee/256, 256>>>(edst);
  k_scan   <<<1, 1024>>>();
  k_scatter<<<Ee/256, 256>>>(edst);
  k_packw  <<<1, 128>>>(l0_lin1, l1_lin1);
  k_packW1 <<<50, 256>>>(W1);

  dim3 gN128(2, 32), gN20(1, 32);

  // ---- layer 0 (D = 64) ----
  gemm_tn<0><<<gN128, 256>>>(0, 64, l0_lin1, 0, 0, 65, nullptr, 4, 128, Nn, 128, 64); // xW
  k_xr   <<<Nn/8, 256>>>(0, 64, l0_attr);
  k_alpha<<<Ee/8, 256>>>(esrc, edst, eattr, 0, l0_attl);
  k_aggr <<<Nn, 128>>>(esrc, eattr, 0);
  gemm_tn<1><<<gN128, 256>>>(1, 128, l0_lin2, 0, 0, 128, l0_bias, 2, 128, Nn, 128, 128); // h1

  // ---- layer 1 (D = 128) ----
  gemm_tn<0><<<gN128, 256>>>(2, 128, l1_lin1, 0, 0, 129, nullptr, 4, 128, Nn, 128, 128); // xW (from h1)
  k_xr   <<<Nn/8, 256>>>(2, 128, l1_attr);
  k_alpha<<<Ee/8, 256>>>(esrc, edst, eattr, 128, l1_attl);
  k_aggr <<<Nn, 128>>>(esrc, eattr, 128);
  gemm_tn<1><<<gN128, 256>>>(1, 128, l1_lin2, 0, 0, 128, l1_bias, 8, 128, Nn, 128, 128); // h2 -> g_h2

  // ---- pairwise head ----
  k_feat<<<(Nn*320 + 255)/256, 256>>>();
  gemm_tn<0><<<gN20, 256>>>(3, 320, nullptr, 7, 0,      320, nullptr, 5, 20, Nn, 20, 320); // a20
  gemm_tn<0><<<gN20, 256>>>(3, 320, nullptr, 7, 20*320, 320, nullptr, 6, 20, Nn, 20, 320); // b20
  k_final<<<Nn/8, 256>>>(b1, W2, b2, m, out);
}

// round 3
// speedup vs baseline: 1.2501x; 1.2501x over previous
#include <cuda_runtime.h>

#define Nn 2048
#define Ee 65536

// ---------------- scratch (device globals; no allocations) ----------------
__device__ __align__(16) float g_feat[Nn*320];     // [x | h1 | h2]
__device__ __align__(16) float g_xWr[Nn*136];      // cols 0..127 = xW, col 128 = xr
__device__ __align__(16) float g_S[Nn*128];
__device__ __align__(16) float g_ealpha[Ee];
__device__ __align__(16) float g_den[Nn];          // invariant: zero at entry (restored by k_aggr)
__device__ __align__(16) float g_ab[Nn*40];        // cols 0..19 = a, 20..39 = b
__device__ __align__(16) float g_W1p[40*320];
__device__ __align__(16) float g_B0p[129*64];      // lin1 rows + att_r row
__device__ __align__(16) float g_B1p[129*128];
__device__ __align__(16) float g_w1e[256];         // per-layer last column of lin1
__device__ int g_deg[Nn];                          // invariant: zero at entry (restored by k_scan)
__device__ int g_off[Nn+1];
__device__ int g_cur[Nn];
__device__ int g_perm[Ee];

__device__ __forceinline__ float lrelu(float x) { return x > 0.f ? x : 0.01f*x; }

__device__ __forceinline__ float* sel_ptr(int s) {
  switch (s) {
    case 0: return g_feat;
    case 1: return g_S;
    case 2: return g_xWr;
    case 3: return g_W1p;
    case 4: return g_B0p;
    case 5: return g_B1p;
    case 6: return g_ab;
    default: return nullptr;
  }
}

// ---------------- fused setup: embed + packs + degree histogram ----------------
__global__ void k_setup(const int* __restrict__ ids, const float* __restrict__ emb,
                        const float* __restrict__ W1,
                        const float* __restrict__ l0_lin1, const float* __restrict__ l1_lin1,
                        const float* __restrict__ l0_attr, const float* __restrict__ l1_attr,
                        const int* __restrict__ edst) {
  int b = blockIdx.x, tid = threadIdx.x;
  if (b < 512) {                     // embedding -> feat cols 0..63
    int node = b*4 + (tid >> 6);
    int col = tid & 63;
    g_feat[node*320 + col] = emb[ids[node]*64 + col];
  } else if (b < 562) {              // pack W1 [40,320]
    int i = (b-512)*256 + tid;
    if (i < 40*320) {
      int r = i/320, c = i - r*320;
      g_W1p[i] = (r < 20) ? W1[r*640 + c] : W1[(r-20)*640 + 320 + c];
    }
  } else if (b == 562) {             // edge-attr weight columns
    if (tid < 128) {
      g_w1e[tid]       = l0_lin1[tid*65  + 64];
      g_w1e[128 + tid] = l1_lin1[tid*129 + 128];
    }
  } else if (b < 596) {              // B0p [129,64] = l0_lin1[:, :64] rows + att_r row
    int i = (b-563)*256 + tid;
    if (i < 129*64) {
      int r = i >> 6, c = i & 63;
      g_B0p[i] = (r < 128) ? l0_lin1[r*65 + c] : l0_attr[c];
    }
  } else if (b < 661) {              // B1p [129,128]
    int i = (b-596)*256 + tid;
    if (i < 129*128) {
      int r = i >> 7, c = i & 127;
      g_B1p[i] = (r < 128) ? l1_lin1[r*129 + c] : l1_attr[c];
    }
  } else {                           // degree histogram (g_deg starts at 0 by invariant)
    int e = (b-661)*256 + tid;
    atomicAdd(&g_deg[edst[e]], 1);
  }
}

// ---------------- scan (2 barriers, shfl-based), restores g_deg=0 ----------------
__global__ void k_scan() {
  int t = threadIdx.x;               // 0..1023, each handles elements 2t, 2t+1
  int d0 = g_deg[2*t], d1 = g_deg[2*t+1];
  int s = d0 + d1;
  int lane = t & 31, wid = t >> 5;
  int v = s;
  #pragma unroll
  for (int o = 1; o < 32; o <<= 1) {
    int u = __shfl_up_sync(0xffffffffu, v, o);
    if (lane >= o) v += u;
  }
  __shared__ int wsum[32];
  if (lane == 31) wsum[wid] = v;
  __syncthreads();
  if (wid == 0) {
    int w = wsum[lane];
    int x = w;
    #pragma unroll
    for (int o = 1; o < 32; o <<= 1) {
      int u = __shfl_up_sync(0xffffffffu, x, o);
      if (lane >= o) x += u;
    }
    wsum[lane] = x - w;              // exclusive warp base
  }
  __syncthreads();
  int excl = wsum[wid] + (v - s);    // exclusive prefix of element 2t
  g_off[2*t]   = excl;       g_cur[2*t]   = excl;
  g_off[2*t+1] = excl + d0;  g_cur[2*t+1] = excl + d0;
  g_deg[2*t] = 0; g_deg[2*t+1] = 0;  // restore invariant for next replay
  if (t == 0) g_off[2048] = Ee;
}

__global__ void k_scatter(const int* __restrict__ edst) {
  int e = blockIdx.x*256 + threadIdx.x;
  int p = atomicAdd(&g_cur[edst[e]], 1);
  g_perm[p] = e;
}

// ---------------- generic GEMM: C[2048,Nc] = act(A @ B^T + bias) ----------------
template<int ACT>
__global__ void gemm_tn(int Asel, int aoff, int lda,
                        const float* __restrict__ Bext, int Bsel, int ldb,
                        const float* __restrict__ bias,
                        int Csel, int coff, int ldc, int Ncols, int K) {
  const float* A = sel_ptr(Asel) + aoff;
  const float* B = Bext ? Bext : sel_ptr(Bsel);
  float* C = sel_ptr(Csel) + coff;
  __shared__ float As[32][65];
  __shared__ float Bs[32][65];
  int tid = threadIdx.x;
  int m0 = blockIdx.y*64, n0 = blockIdx.x*64;
  int tx = tid & 15, ty = tid >> 4;
  float acc[4][4] = {};
  for (int k0 = 0; k0 < K; k0 += 32) {
    #pragma unroll
    for (int i = 0; i < 8; i++) {
      int l = tid + i*256;
      int r = l >> 5, c = l & 31;
      As[c][r] = A[(m0+r)*lda + (k0+c)];
      int rn = n0 + r;
      Bs[c][r] = (rn < Ncols) ? B[rn*ldb + (k0+c)] : 0.f;
    }
    __syncthreads();
    #pragma unroll
    for (int k = 0; k < 32; k++) {
      float av[4], bv[4];
      #pragma unroll
      for (int i = 0; i < 4; i++) av[i] = As[k][ty*4+i];
      #pragma unroll
      for (int j = 0; j < 4; j++) bv[j] = Bs[k][tx*4+j];
      #pragma unroll
      for (int i = 0; i < 4; i++)
        #pragma unroll
        for (int j = 0; j < 4; j++)
          acc[i][j] += av[i]*bv[j];
    }
    __syncthreads();
  }
  #pragma unroll
  for (int i = 0; i < 4; i++) {
    int mm = m0 + ty*4 + i;
    #pragma unroll
    for (int j = 0; j < 4; j++) {
      int nn = n0 + tx*4 + j;
      if (nn < Ncols) {
        float v = acc[i][j];
        if (bias) v += bias[nn];
        if (ACT) v = fmaxf(v, 0.f);
        C[mm*ldc + nn] = v;
      }
    }
  }
}

// ---------------- edge kernels ----------------
// ealpha[e] = exp(leaky(h_e . att_l + xr[dst])); also accumulates denominator
__global__ void k_alpha(const int* __restrict__ esrc, const int* __restrict__ edst,
                        const float* __restrict__ eattr,
                        int w1off, const float* __restrict__ attl) {
  int e = blockIdx.x*8 + (threadIdx.x >> 5);
  int lane = threadIdx.x & 31;
  int src = esrc[e];
  float ea = eattr[e];
  const float4* xw4 = (const float4*)g_xWr;
  const float4* we4 = (const float4*)(g_w1e + w1off);
  const float4* al4 = (const float4*)attl;
  float4 xv = xw4[src*34 + lane];
  float4 wv = we4[lane];
  float4 av = al4[lane];
  float p = lrelu(xv.x + ea*wv.x)*av.x + lrelu(xv.y + ea*wv.y)*av.y
          + lrelu(xv.z + ea*wv.z)*av.z + lrelu(xv.w + ea*wv.w)*av.w;
  #pragma unroll
  for (int s = 16; s > 0; s >>= 1) p += __shfl_xor_sync(0xffffffffu, p, s);
  if (lane == 0) {
    int dst = edst[e];
    float ev = __expf(lrelu(p + g_xWr[dst*136 + 128]));
    g_ealpha[e] = ev;
    atomicAdd(&g_den[dst], ev);
  }
}

// per-dst weighted aggregation; restores g_den=0
__global__ void k_aggr(const int* __restrict__ esrc, const float* __restrict__ eattr,
                       int w1off) {
  int n = blockIdx.x, tid = threadIdx.x;  // 256 threads
  int begin = g_off[n], cnt = g_off[n+1] - begin;
  __shared__ float s_inv;
  if (tid == 0) { s_inv = 1.f/(g_den[n] + 1e-16f); g_den[n] = 0.f; }
  __syncthreads();
  float inv = s_inv;
  int w = tid >> 5, g = tid & 31;     // warp = edge slot, lane = 4-col group
  const float4* xw4 = (const float4*)g_xWr;
  const float4* we4 = (const float4*)(g_w1e + w1off);
  float4 wv = we4[g];
  float ax=0.f, ay=0.f, az=0.f, aw=0.f;
  for (int j0 = 0; j0 < cnt; j0 += 8) {
    int j = j0 + w;
    if (j < cnt) {
      int e = g_perm[begin+j];
      float wt = g_ealpha[e]*inv;
      float ea = eattr[e];
      float4 xv = xw4[esrc[e]*34 + g];
      ax += wt*lrelu(xv.x + ea*wv.x);
      ay += wt*lrelu(xv.y + ea*wv.y);
      az += wt*lrelu(xv.z + ea*wv.z);
      aw += wt*lrelu(xv.w + ea*wv.w);
    }
  }
  __shared__ float4 red4[256];
  red4[tid] = make_float4(ax, ay, az, aw);
  __syncthreads();
  if (w == 0) {
    float4 r = red4[g];
    #pragma unroll
    for (int s = 1; s < 8; s++) {
      float4 o = red4[s*32 + g];
      r.x += o.x; r.y += o.y; r.z += o.z; r.w += o.w;
    }
    ((float4*)g_S)[n*32 + g] = r;
  }
}

// ---------------- fused pairwise MLP + masked row softmax ----------------
__global__ void k_final(const float* __restrict__ b1, const float* __restrict__ W2,
                        const float* __restrict__ b2, const float* __restrict__ m,
                        float* __restrict__ out) {
  const int TI = 8;
  __shared__ float ash[TI][20];
  __shared__ float btile[256][21];
  __shared__ float w2s[20];
  __shared__ float2 red[256];
  __shared__ float rowM[TI], rowInv[TI];
  int tid = threadIdx.x;
  int i0 = blockIdx.x * TI;
  if (tid < TI*20) {
    int r = tid / 20, c = tid - r*20;
    ash[r][c] = g_ab[(i0+r)*40 + c] + b1[c];
  }
  if (tid < 20) w2s[tid] = W2[tid];
  float b2v = b2[0];
  float omax[TI], osum[TI];
  #pragma unroll
  for (int r = 0; r < TI; r++) { omax[r] = -1e30f; osum[r] = 0.f; }

  for (int jt = 0; jt < Nn; jt += 256) {
    __syncthreads();
    #pragma unroll
    for (int u = 0; u < 20; u++) {
      int l = u*256 + tid;
      int t = l / 20, c = l - t*20;
      btile[t][c] = g_ab[(jt+t)*40 + 20 + c];
    }
    __syncthreads();
    int j = jt + tid;
    float bl[20];
    #pragma unroll
    for (int c = 0; c < 20; c++) bl[c] = btile[tid][c];
    #pragma unroll
    for (int r = 0; r < TI; r++) {
      float acc = 0.f;
      #pragma unroll
      for (int c = 0; c < 20; c++) acc += fmaxf(ash[r][c] + bl[c], 0.f) * w2s[c];
      size_t idx = (size_t)(i0+r)*Nn + j;
      float lv = (acc + b2v) * m[idx];
      out[idx] = lv;                       // park raw logit
      float nm = fmaxf(omax[r], lv);       // online softmax
      osum[r] = osum[r]*__expf(omax[r]-nm) + __expf(lv-nm);
      omax[r] = nm;
    }
  }
  for (int r = 0; r < TI; r++) {
    __syncthreads();
    red[tid] = make_float2(omax[r], osum[r]);
    __syncthreads();
    for (int s = 128; s > 0; s >>= 1) {
      if (tid < s) {
        float2 A = red[tid], B = red[tid+s];
        float M = fmaxf(A.x, B.x);
        red[tid] = make_float2(M, A.y*__expf(A.x-M) + B.y*__expf(B.x-M));
      }
      __syncthreads();
    }
    if (tid == 0) { rowM[r] = red[0].x; rowInv[r] = 1.f/red[0].y; }
  }
  __syncthreads();
  for (int jt = 0; jt < Nn; jt += 256) {
    int j = jt + tid;
    #pragma unroll
    for (int r = 0; r < TI; r++) {
      size_t idx = (size_t)(i0+r)*Nn + j;
      out[idx] = __expf(out[idx] - rowM[r]) * rowInv[r];
    }
  }
}

// ---------------- driver ----------------
extern "C" void kernel_launch(void* const* d_in, const int* in_sizes, int n_in,
                              void* d_out, int out_size) {
  const int*   node_ids = (const int*)  d_in[0];
  const int*   eidx     = (const int*)  d_in[1];
  const float* eattr    = (const float*)d_in[2];
  const float* m        = (const float*)d_in[3];
  const float* emb      = (const float*)d_in[4];
  const float* l0_lin1  = (const float*)d_in[5];
  const float* l0_lin2  = (const float*)d_in[6];
  const float* l0_attl  = (const float*)d_in[7];
  const float* l0_attr  = (const float*)d_in[8];
  const float* l0_bias  = (const float*)d_in[9];
  const float* l1_lin1  = (const float*)d_in[10];
  const float* l1_lin2  = (const float*)d_in[11];
  const float* l1_attl  = (const float*)d_in[12];
  const float* l1_attr  = (const float*)d_in[13];
  const float* l1_bias  = (const float*)d_in[14];
  const float* W1       = (const float*)d_in[15];
  const float* b1       = (const float*)d_in[16];
  const float* W2       = (const float*)d_in[17];
  const float* b2       = (const float*)d_in[18];
  float* out = (float*)d_out;
  const int* esrc = eidx;
  const int* edst = eidx + Ee;

  k_setup  <<<917, 256>>>(node_ids, emb, W1, l0_lin1, l1_lin1, l0_attr, l1_attr, edst);
  k_scan   <<<1, 1024>>>();
  k_scatter<<<Ee/256, 256>>>(edst);

  // ---- layer 0 ----
  gemm_tn<0><<<dim3(3,32), 256>>>(0, 0, 320, nullptr, 4, 64, nullptr, 2, 0, 136, 129, 64);   // xW0 + xr
  k_alpha<<<Ee/8, 256>>>(esrc, edst, eattr, 0, l0_attl);
  k_aggr <<<Nn, 256>>>(esrc, eattr, 0);
  gemm_tn<1><<<dim3(2,32), 256>>>(1, 0, 128, l0_lin2, 0, 128, l0_bias, 0, 64, 320, 128, 128); // h1 -> feat

  // ---- layer 1 ----
  gemm_tn<0><<<dim3(3,32), 256>>>(0, 64, 320, nullptr, 5, 128, nullptr, 2, 0, 136, 129, 128); // xW1 + xr
  k_alpha<<<Ee/8, 256>>>(esrc, edst, eattr, 128, l1_attl);
  k_aggr <<<Nn, 256>>>(esrc, eattr, 128);
  gemm_tn<1><<<dim3(2,32), 256>>>(1, 0, 128, l1_lin2, 0, 128, l1_bias, 0, 192, 320, 128, 128); // h2 -> feat

  // ---- pairwise head ----
  gemm_tn<0><<<dim3(1,32), 256>>>(0, 0, 320, nullptr, 3, 320, nullptr, 6, 0, 40, 40, 320);    // a|b
  k_final<<<Nn/8, 256>>>(b1, W2, b2, m, out);
}